// round 2
// baseline (speedup 1.0000x reference)
#include <cuda_runtime.h>
#include <cstdint>

// ---------------- problem constants ----------------
#define T_STEPS 2048
#define BATCH   64
#define FEAT    13
#define HID     300
#define OUT_MAIN (BATCH*T_STEPS*FEAT)   // 1703936
#define OUT_EMB_OFF OUT_MAIN

// ---------------- encoder kernel config ----------------
#define CLUSTER 8
#define HC      38              // hidden units per CTA (8*38=304 >= 300, padded)
#define ROWP    40              // padded rows per gate inside a CTA
#define R3      (3*ROWP)        // 120 gate-rows per CTA (incl. pad)
#define KPAD    304             // hidden dim padded (16*19)
#define NB      4               // batch elements per cluster
#define TENC    256
#define KSPLIT  16
#define KSEG    19              // 16*19 = 304
#define RG      15              // 15 row-groups of 8 rows = 120

#define SM_W (KPAD*R3)          // 36480 floats
#define SM_P (KSPLIT*NB*R3)     // 7680 floats
#define SM_H (2*NB*KPAD)        // 2432 floats
#define SM_X 64
#define SMEM_FLOATS (SM_W+SM_P+SM_H+SM_X)
#define SMEM_BYTES  (SMEM_FLOATS*4)     // 186,624 B

// scratch (no allocation allowed -> device globals)
__device__ float g_hlast[BATCH*HID];
__device__ float g_emb[BATCH*HID];

// ---------------- helpers ----------------
__device__ __forceinline__ float sig_f(float x) {
    return __fdividef(1.f, 1.f + __expf(-x));
}
__device__ __forceinline__ float tanh_f(float x) {
    return 1.f - __fdividef(2.f, __expf(2.f * x) + 1.f);
}
__device__ __forceinline__ unsigned smem_u32(const void* p) {
    unsigned a;
    asm("{ .reg .u64 t; cvta.to.shared.u64 t, %1; cvt.u32.u64 %0, t; }"
        : "=r"(a) : "l"(p));
    return a;
}
__device__ __forceinline__ void cluster_sync_() {
    asm volatile("barrier.cluster.arrive.aligned;" ::: "memory");
    asm volatile("barrier.cluster.wait.aligned;" ::: "memory");
}
__device__ __forceinline__ void st_remote(unsigned addr, int rank, float v) {
    unsigned ra;
    asm("mapa.shared::cluster.u32 %0, %1, %2;" : "=r"(ra) : "r"(addr), "r"(rank));
    asm volatile("st.shared::cluster.f32 [%0], %1;" :: "r"(ra), "f"(v) : "memory");
}

// ======================================================================
// Encoder: persistent clustered GRU. 16 clusters x 8 CTAs, 4 batch / cluster.
// Each CTA owns 38 hidden units (rows r/z/n), full Whh slice in SMEM (k-major).
// Per step: tiled SMEM GEMM -> partials -> gates -> DSMEM h broadcast -> cluster sync.
// ======================================================================
__global__ void __launch_bounds__(TENC, 1) __cluster_dims__(CLUSTER, 1, 1)
enc_kernel(const float* __restrict__ x,
           const float* __restrict__ Wih,
           const float* __restrict__ Whh,
           const float* __restrict__ bih,
           const float* __restrict__ bhh)
{
    extern __shared__ float sm[];
    float* W_s  = sm;                 // [KPAD][R3]  k-major, zero padded
    float* part = sm + SM_W;          // [KSPLIT][NB][R3]
    float* h_s  = part + SM_P;        // [2][NB][KPAD]
    float* x_s  = h_s + SM_H;         // [NB][13]

    const int tid = threadIdx.x;
    unsigned rank;
    asm("mov.u32 %0, %%cluster_ctarank;" : "=r"(rank));
    const int cluster = blockIdx.x / CLUSTER;
    const int bglobal = cluster * NB;

    // ---- load Whh slice transposed+padded into SMEM ----
    for (int idx = tid; idx < SM_W; idx += TENC) {
        int k = idx / R3, row = idx % R3;
        int g = row / ROWP, i = row % ROWP;
        int u = (int)rank * HC + i;
        float v = 0.f;
        if (k < HID && i < HC && u < HID) v = Whh[(g * HID + u) * HID + k];
        W_s[idx] = v;
    }
    // ---- zero h buffers (both, incl. padding) ----
    for (int idx = tid; idx < SM_H; idx += TENC) h_s[idx] = 0.f;

    // ---- gate-role setup (tid < 152): Wih rows + biases in registers ----
    const int gb  = tid / HC;     // batch 0..3
    const int gi_ = tid % HC;     // local unit
    const int u   = (int)rank * HC + gi_;
    const bool gate_ok = (tid < NB * HC) && (u < HID);
    float wih[3][FEAT];
    float brz0 = 0.f, brz1 = 0.f, bin_ = 0.f, bhn_ = 0.f;
    if (gate_ok) {
#pragma unroll
        for (int g = 0; g < 3; g++)
#pragma unroll
            for (int f = 0; f < FEAT; f++)
                wih[g][f] = Wih[(g * HID + u) * FEAT + f];
        brz0 = bih[u]           + bhh[u];
        brz1 = bih[HID + u]     + bhh[HID + u];
        bin_ = bih[2 * HID + u];
        bhn_ = bhh[2 * HID + u];
    }

    // ---- gemm-role setup (tid < 240) ----
    const int ks = tid / RG;          // 0..15
    const int rg = tid % RG;          // 0..14
    const bool gemm_ok = (tid < KSPLIT * RG);

    const unsigned h_base_u32 = smem_u32(h_s);

    cluster_sync_();   // W_s + zeroed h visible cluster-wide before step 0

    float h_keep = 0.f;

    for (int t = 0; t < T_STEPS; t++) {
        const int p = t & 1;

        // prefetch x_t (52 values) into registers
        float xv = 0.f;
        if (tid < NB * FEAT) {
            int b = tid / FEAT, f = tid % FEAT;
            xv = __ldg(&x[((bglobal + b) * T_STEPS + t) * FEAT + f]);
        }

        if (gemm_ok) {
            float acc[NB][8];
#pragma unroll
            for (int b = 0; b < NB; b++)
#pragma unroll
                for (int j = 0; j < 8; j++) acc[b][j] = 0.f;

            const float* hp = h_s + p * NB * KPAD;
            const int k0 = ks * KSEG;
#pragma unroll
            for (int kk = 0; kk < KSEG; kk++) {
                const int k = k0 + kk;
                const float4 w0 = *(const float4*)(W_s + k * R3 + rg * 8);
                const float4 w1 = *(const float4*)(W_s + k * R3 + rg * 8 + 4);
#pragma unroll
                for (int b = 0; b < NB; b++) {
                    const float hv = hp[b * KPAD + k];
                    acc[b][0] = fmaf(hv, w0.x, acc[b][0]);
                    acc[b][1] = fmaf(hv, w0.y, acc[b][1]);
                    acc[b][2] = fmaf(hv, w0.z, acc[b][2]);
                    acc[b][3] = fmaf(hv, w0.w, acc[b][3]);
                    acc[b][4] = fmaf(hv, w1.x, acc[b][4]);
                    acc[b][5] = fmaf(hv, w1.y, acc[b][5]);
                    acc[b][6] = fmaf(hv, w1.z, acc[b][6]);
                    acc[b][7] = fmaf(hv, w1.w, acc[b][7]);
                }
            }
            // store partials
#pragma unroll
            for (int b = 0; b < NB; b++) {
                float* pp = part + (ks * NB + b) * R3 + rg * 8;
                *(float4*)pp       = make_float4(acc[b][0], acc[b][1], acc[b][2], acc[b][3]);
                *(float4*)(pp + 4) = make_float4(acc[b][4], acc[b][5], acc[b][6], acc[b][7]);
            }
        }
        if (tid < NB * FEAT) x_s[tid] = xv;

        __syncthreads();

        if (gate_ok) {
            float s0 = 0.f, s1 = 0.f, s2 = 0.f;
#pragma unroll
            for (int q = 0; q < KSPLIT; q++) {
                const float* pq = part + (q * NB + gb) * R3;
                s0 += pq[gi_];
                s1 += pq[ROWP + gi_];
                s2 += pq[2 * ROWP + gi_];
            }
            float x0 = 0.f, x1 = 0.f, x2 = 0.f;
            const float* xb = x_s + gb * FEAT;
#pragma unroll
            for (int f = 0; f < FEAT; f++) {
                const float xf = xb[f];
                x0 = fmaf(wih[0][f], xf, x0);
                x1 = fmaf(wih[1][f], xf, x1);
                x2 = fmaf(wih[2][f], xf, x2);
            }
            const float r = sig_f(x0 + s0 + brz0);
            const float z = sig_f(x1 + s1 + brz1);
            const float n = tanh_f(x2 + bin_ + r * (s2 + bhn_));
            const float hold = h_s[p * NB * KPAD + gb * KPAD + u];
            const float hn = (1.f - z) * n + z * hold;
            h_keep = hn;
            // broadcast new h element to all 8 CTAs' next buffer
            const unsigned addr = h_base_u32
                + (((p ^ 1) * NB + gb) * KPAD + u) * 4u;
#pragma unroll
            for (int c = 0; c < CLUSTER; c++) st_remote(addr, c, hn);
        }

        cluster_sync_();
    }

    if (gate_ok) g_hlast[(bglobal + gb) * HID + u] = h_keep;
}

// ======================================================================
// fc + relu: emb[b][j] = relu(fc_W[j,:] . hlast[b,:] + fc_b[j])
// ======================================================================
__global__ void __launch_bounds__(128) fc_kernel(
    const float* __restrict__ fcW, const float* __restrict__ fcb,
    float* __restrict__ dout, int write_emb)
{
    __shared__ float hs[HID];
    const int b = blockIdx.x;
    const int tid = threadIdx.x;
    for (int k = tid; k < HID; k += 128) hs[k] = g_hlast[b * HID + k];
    __syncthreads();
    for (int j = tid; j < HID; j += 128) {
        float a = fcb[j];
        const float* w = fcW + j * HID;
#pragma unroll 4
        for (int k = 0; k < HID; k++) a = fmaf(w[k], hs[k], a);
        a = fmaxf(a, 0.f);
        g_emb[b * HID + j] = a;
        if (write_emb) dout[OUT_EMB_OFF + b * HID + j] = a;
    }
}

// ======================================================================
// Decoder: one CTA per batch element, hidden=13, constant input emb.
// ======================================================================
__global__ void __launch_bounds__(64) dec_kernel(
    const float* __restrict__ dWih, const float* __restrict__ dWhh,
    const float* __restrict__ dbih, const float* __restrict__ dbhh,
    float* __restrict__ out)
{
    __shared__ float embs[HID];
    __shared__ float dgi[3 * FEAT];
    __shared__ float ghs[3 * FEAT];
    __shared__ float hs[FEAT];

    const int b = blockIdx.x;
    const int tid = threadIdx.x;

    for (int k = tid; k < HID; k += 64) embs[k] = g_emb[b * HID + k];
    if (tid < FEAT) hs[tid] = 0.f;
    __syncthreads();

    float wreg[FEAT];
    float bhhj = 0.f;
    if (tid < 3 * FEAT) {
        float a = dbih[tid];
        const float* w = dWih + tid * HID;
#pragma unroll 4
        for (int k = 0; k < HID; k++) a = fmaf(w[k], embs[k], a);
        dgi[tid] = a;
#pragma unroll
        for (int k = 0; k < FEAT; k++) wreg[k] = dWhh[tid * FEAT + k];
        bhhj = dbhh[tid];
    }
    __syncthreads();

    float* ob = out + b * T_STEPS * FEAT;
    for (int t = 0; t < T_STEPS; t++) {
        if (tid < 3 * FEAT) {
            float a = bhhj;
#pragma unroll
            for (int k = 0; k < FEAT; k++) a = fmaf(wreg[k], hs[k], a);
            ghs[tid] = a;
        }
        __syncthreads();
        if (tid < FEAT) {
            const float r = sig_f(dgi[tid] + ghs[tid]);
            const float z = sig_f(dgi[FEAT + tid] + ghs[FEAT + tid]);
            const float n = tanh_f(dgi[2 * FEAT + tid] + r * ghs[2 * FEAT + tid]);
            const float hn = (1.f - z) * n + z * hs[tid];
            hs[tid] = hn;
            ob[t * FEAT + tid] = hn;
        }
        __syncthreads();
    }
}

// ======================================================================
// launch
// ======================================================================
extern "C" void kernel_launch(void* const* d_in, const int* in_sizes, int n_in,
                              void* d_out, int out_size)
{
    const float* x        = (const float*)d_in[0];
    const float* enc_Wih  = (const float*)d_in[1];
    const float* enc_Whh  = (const float*)d_in[2];
    const float* enc_bih  = (const float*)d_in[3];
    const float* enc_bhh  = (const float*)d_in[4];
    const float* fc_W     = (const float*)d_in[5];
    const float* fc_b     = (const float*)d_in[6];
    const float* dec_Wih  = (const float*)d_in[7];
    const float* dec_Whh  = (const float*)d_in[8];
    const float* dec_bih  = (const float*)d_in[9];
    const float* dec_bhh  = (const float*)d_in[10];
    float* out = (float*)d_out;

    const int write_emb = (out_size >= OUT_MAIN + BATCH * HID) ? 1 : 0;

    cudaFuncSetAttribute(enc_kernel,
                         cudaFuncAttributeMaxDynamicSharedMemorySize, SMEM_BYTES);

    enc_kernel<<<(BATCH / NB) * CLUSTER, TENC, SMEM_BYTES>>>(
        x, enc_Wih, enc_Whh, enc_bih, enc_bhh);
    fc_kernel<<<BATCH, 128>>>(fc_W, fc_b, out, write_emb);
    dec_kernel<<<BATCH, 64>>>(dec_Wih, dec_Whh, dec_bih, dec_bhh, out);
}

// round 3
// speedup vs baseline: 1.1842x; 1.1842x over previous
#include <cuda_runtime.h>
#include <cstdint>

typedef unsigned long long ull;

// ---------------- problem constants ----------------
#define T_STEPS 2048
#define BATCH   64
#define FEAT    13
#define HID     300
#define OUT_MAIN (BATCH*T_STEPS*FEAT)
#define OUT_EMB_OFF OUT_MAIN

// ---------------- encoder config ----------------
#define CLUSTER 8
#define NB      4               // batch per cluster
#define TENC    512
#define HC      38              // hidden units per CTA (8*38=304)
#define ROWP    40              // padded rows per gate
#define R3      120             // 3*ROWP
#define KTOT    320             // 300 h + 4 pad + 13 x + 3 pad
#define KP2     160             // k-pairs
#define KSPLIT  8
#define KSEG2   20              // k-pairs per split
#define RG      60              // row-groups (2 rows each) -> 8*60=480 gemm threads
#define XSLOT   152             // first k-pair index of x block (k=304)

__device__ float g_hlast[BATCH*HID];
__device__ float g_emb[BATCH*HID];

// ---------------- helpers ----------------
__device__ __forceinline__ float sig_f(float x) {
    return __fdividef(1.f, 1.f + __expf(-x));
}
__device__ __forceinline__ float tanh_f(float x) {
    return 1.f - __fdividef(2.f, __expf(2.f * x) + 1.f);
}
__device__ __forceinline__ unsigned smem_u32(const void* p) {
    unsigned a;
    asm("{ .reg .u64 t; cvta.to.shared.u64 t, %1; cvt.u32.u64 %0, t; }"
        : "=r"(a) : "l"(p));
    return a;
}
__device__ __forceinline__ void cluster_sync_() {
    asm volatile("barrier.cluster.arrive.aligned;" ::: "memory");
    asm volatile("barrier.cluster.wait.aligned;" ::: "memory");
}
__device__ __forceinline__ void st_remote(unsigned addr, int rank, float v) {
    unsigned ra;
    asm("mapa.shared::cluster.u32 %0, %1, %2;" : "=r"(ra) : "r"(addr), "r"(rank));
    asm volatile("st.shared::cluster.f32 [%0], %1;" :: "r"(ra), "f"(v) : "memory");
}
__device__ __forceinline__ ull pk2(float lo, float hi) {
    ull r;
    asm("mov.b64 %0, {%1, %2};" : "=l"(r) : "f"(lo), "f"(hi));
    return r;
}
__device__ __forceinline__ void fma2(ull& d, ull a, ull b) {
    asm("fma.rn.f32x2 %0, %1, %2, %0;" : "+l"(d) : "l"(a), "l"(b));
}
__device__ __forceinline__ float upks(ull v) {
    float lo, hi;
    asm("mov.b64 {%0, %1}, %2;" : "=f"(lo), "=f"(hi) : "l"(v));
    return lo + hi;
}

// weight fetch with x-fold: k<300 -> Whh, 304<=k<317 && g<2 -> Wih, else 0
__device__ __forceinline__ float wval(const float* __restrict__ Wih,
                                      const float* __restrict__ Whh,
                                      int g, int u, int k) {
    if (k < HID) return Whh[(g * HID + u) * HID + k];
    if (k >= 304 && k < 304 + FEAT && g < 2) return Wih[(g * HID + u) * FEAT + (k - 304)];
    return 0.f;
}

// ======================================================================
// Encoder: 16 clusters x 8 CTAs, 4 batch/cluster, Whh slice in REGISTERS
// (packed f32x2 along k), per-step: reg GEMM -> partials -> gates ->
// scalar DSMEM h broadcast -> cluster sync. r/z input GEMM folded into k.
// ======================================================================
__global__ void __launch_bounds__(TENC, 1) __cluster_dims__(CLUSTER, 1, 1)
enc_kernel(const float* __restrict__ x,
           const float* __restrict__ Wih,
           const float* __restrict__ Whh,
           const float* __restrict__ bih,
           const float* __restrict__ bhh)
{
    __shared__ float  part[NB][R3][KSPLIT];   // partial sums, [b][row][ksplit]
    __shared__ float2 h2[2][NB][KP2];         // h (+x) pairs, double buffered
    __shared__ float  in_s[NB * HC];          // n-gate input dots
    __shared__ float  win_s[HC][14];          // Wih n-gate rows (this CTA's units)

    const int tid = threadIdx.x;
    unsigned rank;
    asm("mov.u32 %0, %%cluster_ctarank;" : "=r"(rank));
    const int bg = (blockIdx.x / CLUSTER) * NB;

    // ---- zero h2 (both buffers, all slots) ----
    {
        float* h2f = (float*)h2;
        for (int i = tid; i < 2 * NB * KP2 * 2; i += TENC) h2f[i] = 0.f;
    }
    // ---- win_s: n-gate Wih rows for this CTA's units ----
    for (int i = tid; i < HC * 14; i += TENC) {
        int r = i / 14, f = i % 14;
        int u = (int)rank * HC + r;
        win_s[r][f] = (f < FEAT && u < HID) ? Wih[(2 * HID + u) * FEAT + f] : 0.f;
    }

    // ---- gemm role: weights into registers ----
    const int ks = tid / RG;
    const int rg = tid % RG;
    const bool gemm_ok = tid < KSPLIT * RG;    // 480 threads
    const int row0 = rg * 2;
    ull w0[KSEG2], w1[KSEG2];
    if (gemm_ok) {
        {
            int row = row0;
            int g = row / ROWP, i = row % ROWP, u = (int)rank * HC + i;
            bool ok = (i < HC) && (u < HID);
#pragma unroll
            for (int kp = 0; kp < KSEG2; kp++) {
                int k0 = (ks * KSEG2 + kp) * 2;
                float a = ok ? wval(Wih, Whh, g, u, k0) : 0.f;
                float b = ok ? wval(Wih, Whh, g, u, k0 + 1) : 0.f;
                w0[kp] = pk2(a, b);
            }
        }
        {
            int row = row0 + 1;
            int g = row / ROWP, i = row % ROWP, u = (int)rank * HC + i;
            bool ok = (i < HC) && (u < HID);
#pragma unroll
            for (int kp = 0; kp < KSEG2; kp++) {
                int k0 = (ks * KSEG2 + kp) * 2;
                float a = ok ? wval(Wih, Whh, g, u, k0) : 0.f;
                float b = ok ? wval(Wih, Whh, g, u, k0 + 1) : 0.f;
                w1[kp] = pk2(a, b);
            }
        }
    }

    // ---- gate role (tid < 152, subset of gemm threads) ----
    const int gb = tid / HC;
    const int gi_ = tid % HC;
    const int u = (int)rank * HC + gi_;
    const bool gate_ok = (tid < NB * HC) && (u < HID);
    float brz0 = 0.f, brz1 = 0.f, bin_ = 0.f, bhn_ = 0.f, h_keep = 0.f;
    if (gate_ok) {
        brz0 = bih[u]           + bhh[u];
        brz1 = bih[HID + u]     + bhh[HID + u];
        bin_ = bih[2 * HID + u];
        bhn_ = bhh[2 * HID + u];
    }

    // ---- aux role (tid >= 480): n-gate input dots + x staging ----
    const int lane = tid - KSPLIT * RG;
    const bool aux_ok = tid >= KSPLIT * RG;
    int xb_ = 0, xfp = 0;
    if (aux_ok && lane < NB * 7) { xb_ = lane / 7; xfp = lane % 7; }

    // pre-stage x[0] into buffer 0 (local)
    if (aux_ok && lane < NB * 7) {
        const float* xp = x + ((long)(bg + xb_) * T_STEPS + 0) * FEAT + 2 * xfp;
        float a = xp[0];
        float b = (2 * xfp + 1 < FEAT) ? xp[1] : 0.f;
        h2[0][xb_][XSLOT + xfp] = make_float2(a, b);
    }

    const unsigned h_base = smem_u32(h2);

    cluster_sync_();

    for (int t = 0; t < T_STEPS; t++) {
        const int p = t & 1;
        float xa = 0.f, xbv = 0.f;

        if (gemm_ok) {
            ull a00 = 0ull, a01 = 0ull, a10 = 0ull, a11 = 0ull;
            ull a20 = 0ull, a21 = 0ull, a30 = 0ull, a31 = 0ull;
            const ull* hp = (const ull*)&h2[p][0][ks * KSEG2];
#pragma unroll
            for (int kp = 0; kp < KSEG2; kp++) {
                ull hv0 = hp[kp];
                ull hv1 = hp[kp + KP2];
                ull hv2 = hp[kp + 2 * KP2];
                ull hv3 = hp[kp + 3 * KP2];
                fma2(a00, w0[kp], hv0); fma2(a01, w1[kp], hv0);
                fma2(a10, w0[kp], hv1); fma2(a11, w1[kp], hv1);
                fma2(a20, w0[kp], hv2); fma2(a21, w1[kp], hv2);
                fma2(a30, w0[kp], hv3); fma2(a31, w1[kp], hv3);
            }
            part[0][row0][ks] = upks(a00); part[0][row0 + 1][ks] = upks(a01);
            part[1][row0][ks] = upks(a10); part[1][row0 + 1][ks] = upks(a11);
            part[2][row0][ks] = upks(a20); part[2][row0 + 1][ks] = upks(a21);
            part[3][row0][ks] = upks(a30); part[3][row0 + 1][ks] = upks(a31);
        } else {
            // aux: n-gate input dots from x[t] (in h2[p] x-slots)
            for (int gidx = lane; gidx < NB * HC; gidx += 32) {
                int b = gidx / HC, i = gidx % HC;
                float s = 0.f;
#pragma unroll
                for (int fp = 0; fp < 7; fp++) {
                    float2 xp = h2[p][b][XSLOT + fp];
                    s = fmaf(win_s[i][2 * fp],     xp.x, s);
                    s = fmaf(win_s[i][2 * fp + 1], xp.y, s);
                }
                in_s[gidx] = s;
            }
            // prefetch x[t+1]
            if (lane < NB * 7 && t + 1 < T_STEPS) {
                const float* xp = x + ((long)(bg + xb_) * T_STEPS + (t + 1)) * FEAT + 2 * xfp;
                xa = __ldg(xp);
                xbv = (2 * xfp + 1 < FEAT) ? __ldg(xp + 1) : 0.f;
            }
        }

        __syncthreads();

        if (gate_ok) {
            const float* pr = &part[gb][gi_][0];
            float4 r0 = *(const float4*)pr, r1 = *(const float4*)(pr + 4);
            float s0 = (r0.x + r0.y) + (r0.z + r0.w) + (r1.x + r1.y) + (r1.z + r1.w);
            pr = &part[gb][ROWP + gi_][0];
            r0 = *(const float4*)pr; r1 = *(const float4*)(pr + 4);
            float s1 = (r0.x + r0.y) + (r0.z + r0.w) + (r1.x + r1.y) + (r1.z + r1.w);
            pr = &part[gb][2 * ROWP + gi_][0];
            r0 = *(const float4*)pr; r1 = *(const float4*)(pr + 4);
            float s2 = (r0.x + r0.y) + (r0.z + r0.w) + (r1.x + r1.y) + (r1.z + r1.w);

            float i_n = in_s[tid];
            float r = sig_f(s0 + brz0);
            float z = sig_f(s1 + brz1);
            float n = tanh_f(i_n + bin_ + r * (s2 + bhn_));
            float hn = (1.f - z) * n + z * h_keep;
            h_keep = hn;

            // broadcast scalar h to all 8 CTAs' next buffer
            unsigned addr = h_base
                + ((unsigned)((p ^ 1) * NB + gb) * KP2) * 8u + (unsigned)u * 4u;
#pragma unroll
            for (int c = 0; c < CLUSTER; c++) st_remote(addr, c, hn);
        }
        if (aux_ok && lane < NB * 7 && t + 1 < T_STEPS)
            h2[p ^ 1][xb_][XSLOT + xfp] = make_float2(xa, xbv);

        cluster_sync_();
    }

    if (gate_ok) g_hlast[(bg + gb) * HID + u] = h_keep;
}

// ======================================================================
// fc + relu
// ======================================================================
__global__ void __launch_bounds__(128) fc_kernel(
    const float* __restrict__ fcW, const float* __restrict__ fcb,
    float* __restrict__ dout, int write_emb)
{
    __shared__ float hs[HID];
    const int b = blockIdx.x;
    const int tid = threadIdx.x;
    for (int k = tid; k < HID; k += 128) hs[k] = g_hlast[b * HID + k];
    __syncthreads();
    for (int j = tid; j < HID; j += 128) {
        float a = fcb[j];
        const float* w = fcW + j * HID;
#pragma unroll 4
        for (int k = 0; k < HID; k++) a = fmaf(w[k], hs[k], a);
        a = fmaxf(a, 0.f);
        g_emb[b * HID + j] = a;
        if (write_emb) dout[OUT_EMB_OFF + b * HID + j] = a;
    }
}

// ======================================================================
// Decoder: one warp per batch element, h broadcast via shfl, no smem/bar.
// ======================================================================
__global__ void __launch_bounds__(32) dec_kernel(
    const float* __restrict__ dWih, const float* __restrict__ dWhh,
    const float* __restrict__ dbih, const float* __restrict__ dbhh,
    float* __restrict__ out)
{
    const int b = blockIdx.x;
    const int lane = threadIdx.x;

    float wr[FEAT], wz[FEAT], wn[FEAT];
    float gr0 = 0.f, gz0 = 0.f, gn0 = 0.f, bhn = 0.f, h = 0.f;

    if (lane < FEAT) {
        gr0 = dbih[lane]            + dbhh[lane];
        gz0 = dbih[FEAT + lane]     + dbhh[FEAT + lane];
        gn0 = dbih[2 * FEAT + lane];
        bhn = dbhh[2 * FEAT + lane];
        const float* e  = g_emb + b * HID;
        const float* w0 = dWih + lane * HID;
        const float* w1 = dWih + (FEAT + lane) * HID;
        const float* w2 = dWih + (2 * FEAT + lane) * HID;
#pragma unroll 4
        for (int k = 0; k < HID; k++) {
            float ev = e[k];
            gr0 = fmaf(w0[k], ev, gr0);
            gz0 = fmaf(w1[k], ev, gz0);
            gn0 = fmaf(w2[k], ev, gn0);
        }
#pragma unroll
        for (int k = 0; k < FEAT; k++) {
            wr[k] = dWhh[lane * FEAT + k];
            wz[k] = dWhh[(FEAT + lane) * FEAT + k];
            wn[k] = dWhh[(2 * FEAT + lane) * FEAT + k];
        }
    }

    float* ob = out + (long)b * T_STEPS * FEAT;
    for (int t = 0; t < T_STEPS; t++) {
        float sr = 0.f, sz = 0.f, sn = 0.f;
#pragma unroll
        for (int k = 0; k < FEAT; k++) {
            float hk = __shfl_sync(0xffffffffu, h, k);
            sr = fmaf(wr[k], hk, sr);
            sz = fmaf(wz[k], hk, sz);
            sn = fmaf(wn[k], hk, sn);
        }
        if (lane < FEAT) {
            float r = sig_f(gr0 + sr);
            float z = sig_f(gz0 + sz);
            float n = tanh_f(gn0 + r * (sn + bhn));
            h = (1.f - z) * n + z * h;
            ob[t * FEAT + lane] = h;
        }
    }
}

// ======================================================================
// launch
// ======================================================================
extern "C" void kernel_launch(void* const* d_in, const int* in_sizes, int n_in,
                              void* d_out, int out_size)
{
    const float* x        = (const float*)d_in[0];
    const float* enc_Wih  = (const float*)d_in[1];
    const float* enc_Whh  = (const float*)d_in[2];
    const float* enc_bih  = (const float*)d_in[3];
    const float* enc_bhh  = (const float*)d_in[4];
    const float* fc_W     = (const float*)d_in[5];
    const float* fc_b     = (const float*)d_in[6];
    const float* dec_Wih  = (const float*)d_in[7];
    const float* dec_Whh  = (const float*)d_in[8];
    const float* dec_bih  = (const float*)d_in[9];
    const float* dec_bhh  = (const float*)d_in[10];
    float* out = (float*)d_out;

    const int write_emb = (out_size >= OUT_MAIN + BATCH * HID) ? 1 : 0;

    enc_kernel<<<(BATCH / NB) * CLUSTER, TENC>>>(
        x, enc_Wih, enc_Whh, enc_bih, enc_bhh);
    fc_kernel<<<BATCH, 128>>>(fc_W, fc_b, out, write_emb);
    dec_kernel<<<BATCH, 32>>>(dec_Wih, dec_Whh, dec_bih, dec_bhh, out);
}